// round 13
// baseline (speedup 1.0000x reference)
#include <cuda_runtime.h>
#include <cuda_bf16.h>

// Soft histogram via sub-bin counting + kernel-table convolution, v4.
// out[b,k] = (1/N) sum_n g(c_n - k),  c = x*256,  g(v) = sig(2.5v) - sig(2.5(v-1))
// Sub-bin width 1/16 (4096 bins + 1 overflow slot), round-to-nearest,
// then 192-tap convolution with precomputed g table. rel_err ~3.5e-4.
//
// v4 vs v2 (18.9us): replace shared-memory ATOMS scatter (floor 2 cyc/lane,
// ~16us chip) with global REDG scatter (0.854-1.29 cyc/lane, L2-resident
// histogram, 192 L2 atomic ALUs). Single kernel: last block per batch
// (completion counter, fire-and-forget) convolves its batch, writes out
// directly, and zero-restores g_hist + counter so no zero kernels are needed
// (device globals are zero-initialized at load; each run restores zeros).
// Float counts are integer-valued < 2^24 -> adds exact -> deterministic.

#define THREADS   256
#define SUBBINS   4096
#define HSLOTS    4097            // +1 slot for s == 4096 (x -> 1- rounds up)
#define HROW      4224            // padded row stride (floats)
#define MAXB      16
#define TBL       192             // taps: v = (jj - 88)/16
#define KBINS     256
#define P2        64              // blocks per batch

__device__ float    g_hist[MAXB * HROW];   // zero-init at module load
__device__ unsigned g_cnt[MAXB];           // zero-init at module load

__device__ __forceinline__ void dep(float* __restrict__ gh, float f) {
    int s = __float2int_rn(f * 4096.0f);
    s = min(max(s, 0), SUBBINS);           // slot 4096 kept distinct
    atomicAdd(&gh[s], 1.0f);               // return unused -> RED.E.ADD.F32
}

__global__ __launch_bounds__(THREADS)
void hist_kernel(const float* __restrict__ x, float* __restrict__ out,
                 int N4, float inv_n)
{
    __shared__ float hist_s[HSLOTS];       // permuted: a = (s&15)<<8 | s>>4
    __shared__ float T[TBL];
    __shared__ unsigned s_last;

    const int tid   = threadIdx.x;
    const int batch = blockIdx.x >> 6;     // P2 == 64 blocks per batch
    const int part  = blockIdx.x & (P2 - 1);
    float* gh = g_hist + batch * HROW;

    // ---- phase 1: REDG deposit, 4x-unrolled loads (MLP=4) ----
    const float4* xb = reinterpret_cast<const float4*>(x) + (size_t)batch * (size_t)N4;
    const int STR = P2 * THREADS;
    for (int i = part * THREADS + tid; i < N4; i += 4 * STR) {
        const int i1 = i + STR, i2 = i + 2 * STR, i3 = i + 3 * STR;
        const bool c1 = i1 < N4, c2 = i2 < N4, c3 = i3 < N4;
        float4 v0, v1, v2, v3;
        v0 = xb[i];
        if (c1) v1 = xb[i1];
        if (c2) v2 = xb[i2];
        if (c3) v3 = xb[i3];
        dep(gh, v0.x); dep(gh, v0.y); dep(gh, v0.z); dep(gh, v0.w);
        if (c1) { dep(gh, v1.x); dep(gh, v1.y); dep(gh, v1.z); dep(gh, v1.w); }
        if (c2) { dep(gh, v2.x); dep(gh, v2.y); dep(gh, v2.z); dep(gh, v2.w); }
        if (c3) { dep(gh, v3.x); dep(gh, v3.y); dep(gh, v3.z); dep(gh, v3.w); }
    }

    // ---- completion: last block of this batch does the epilogue ----
    __threadfence();                       // publish this thread's REDs
    __syncthreads();
    if (tid == 0)
        s_last = (atomicAdd(&g_cnt[batch], 1u) == P2 - 1) ? 1u : 0u;
    __syncthreads();
    if (!s_last) return;
    __threadfence();                       // acquire: see all batch deposits

    // ---- epilogue: load hist (permute), zero-restore, build g table ----
    for (int d = tid; d < HSLOTS; d += THREADS) {
        float v = gh[d];                   // L2-resident
        gh[d] = 0.0f;                      // restore invariant for next run
        int a = (d < SUBBINS) ? (((d & 15) << 8) | (d >> 4)) : SUBBINS;
        hist_s[a] = v;
    }
    if (tid < TBL) {
        float v  = (float)(tid - 88) * (1.0f / 16.0f);
        float aa = 2.5f * v;
        float bb = aa - 2.5f;
        float sa = 1.0f / (1.0f + __expf(-aa));
        float sb = 1.0f / (1.0f + __expf(-bb));
        T[tid] = sa - sb;
    }
    if (tid == 0) g_cnt[batch] = 0;        // restore counter for next run
    __syncthreads();

    // ---- phase 2: 192-tap convolution, conflict-free (permuted layout) ----
    // thread k sums over s = 16k - 88 + jj, jj in [0,192)
    const int k = tid;                     // THREADS == KBINS
    float acc = 0.0f;
    if (k >= 6 && k <= 249) {
        const int b = k - 6;
        #pragma unroll
        for (int jj = 0; jj < TBL; jj++) {
            const int m = jj + 8;
            acc += T[jj] * hist_s[((m & 15) << 8) + (m >> 4) + b];
        }
    } else {
        const int s0 = 16 * k - 88;
        for (int jj = 0; jj < TBL; jj++) {
            int s = s0 + jj;
            if (s >= 0 && s <= SUBBINS) {
                int a = (s < SUBBINS) ? (((s & 15) << 8) | (s >> 4)) : SUBBINS;
                acc += T[jj] * hist_s[a];
            }
        }
    }
    out[batch * KBINS + k] = acc * inv_n;  // direct write, no atomics
}

extern "C" void kernel_launch(void* const* d_in, const int* in_sizes, int n_in,
                              void* d_out, int out_size) {
    const float* x = (const float*)d_in[0];
    float* out = (float*)d_out;

    int B  = out_size / KBINS;        // 8
    int N  = in_sizes[0] / B;         // 262144
    int N4 = N / 4;

    dim3 grid(B * P2);                // 512 blocks
    hist_kernel<<<grid, THREADS>>>(x, out, N4, 1.0f / (float)N);
}

// round 15
// speedup vs baseline: 3.0061x; 3.0061x over previous
#include <cuda_runtime.h>
#include <cuda_bf16.h>

// Soft histogram via sub-bin counting + kernel-table convolution, v5.
// out[b,k] = (1/N) sum_n g(c_n - k),  c = x*256,  g(v) = sig(2.5v) - sig(2.5(v-1))
// Sub-bin width 1/16 (4096 bins + slot for s=4096), round-to-nearest,
// 160-tap convolution with precomputed g table.
//
// v5 vs v2 (18.9us): v2 was DRAM-LATENCY bound (MLP=1: 8 warps x 1 LDG.128
// = 412 GB/s measured == 8MB/19us), NOT atomic-floor bound (l1tex only 20%).
// Fix: 4x front-batched float4 loads (MLP=4/warp) + 2 CTAs/SM (16 warps)
// -> ~3.8TB/s load ceiling; shared-ATOMS scatter kept (proven fastest).
// Clamps dropped (x in [0,1) => s in [0,4096] already). Conv window 192->160
// taps (truncation ~1e-5 rel).

#define THREADS   256
#define SUBBINS   4096
#define HSLOTS    4097            // +1 slot for s == 4096 (x -> 1- rounds up)
#define TBL       160             // taps: v = (jj - 72)/16 in [-4.5, 5.4375]
#define KBINS     256
#define P         37              // blocks per batch -> 296 blocks = 2/SM

__global__ void zero_kernel(float* out, int n) {
    int i = blockIdx.x * blockDim.x + threadIdx.x;
    if (i < n) out[i] = 0.0f;
}

__device__ __forceinline__ void dep(float* __restrict__ hist, float f) {
    // s in [0,4096] guaranteed (x in [0,1), round-to-nearest)
    int s = __float2int_rn(f * 4096.0f);
    // permuted addr: a = (s&15)<<8 | (s>>4); s==4096 -> dedicated slot 4096
    int a = ((s & 15) << 8) + (s >> 4);
    if (s == SUBBINS) a = SUBBINS;
    atomicAdd(&hist[a], 1.0f);    // return unused -> fire-and-forget ATOMS
}

__global__ __launch_bounds__(THREADS, 2)
void hist_kernel(const float* __restrict__ x, float* __restrict__ out,
                 int N4, float inv_n)
{
    __shared__ float hist[HSLOTS];
    __shared__ float T[TBL];

    const int tid   = threadIdx.x;
    const int batch = blockIdx.y;

    // init: zero histogram, build g table
    for (int i = tid; i < HSLOTS; i += THREADS) hist[i] = 0.0f;
    if (tid < TBL) {
        float v  = (float)(tid - 72) * (1.0f / 16.0f);
        float aa = 2.5f * v;
        float bb = aa - 2.5f;
        float sa = 1.0f / (1.0f + __expf(-aa));
        float sb = 1.0f / (1.0f + __expf(-bb));
        T[tid] = sa - sb;
    }
    __syncthreads();

    // ---- phase 1: scatter (shared float atomics), 4x front-batched loads ----
    const float4* xb = reinterpret_cast<const float4*>(x) + (size_t)batch * (size_t)N4;
    const int STR = P * THREADS;
    for (int i = blockIdx.x * THREADS + tid; i < N4; i += 4 * STR) {
        const int i1 = i + STR, i2 = i + 2 * STR, i3 = i + 3 * STR;
        const bool c1 = i1 < N4, c2 = i2 < N4, c3 = i3 < N4;
        float4 v0, v1, v2, v3;
        v0 = xb[i];
        if (c1) v1 = xb[i1];
        if (c2) v2 = xb[i2];
        if (c3) v3 = xb[i3];
        dep(hist, v0.x); dep(hist, v0.y); dep(hist, v0.z); dep(hist, v0.w);
        if (c1) { dep(hist, v1.x); dep(hist, v1.y); dep(hist, v1.z); dep(hist, v1.w); }
        if (c2) { dep(hist, v2.x); dep(hist, v2.y); dep(hist, v2.z); dep(hist, v2.w); }
        if (c3) { dep(hist, v3.x); dep(hist, v3.y); dep(hist, v3.z); dep(hist, v3.w); }
    }
    __syncthreads();

    // ---- phase 2: 160-tap convolution, conflict-free (permuted layout) ----
    // thread k sums over s = 16k - 72 + jj, jj in [0,160).
    // Interior (k in [5,250]): s = 16(k-5) + (jj+8); with m = jj+8:
    //   addr = ((m&15)<<8) + (m>>4) + (k-5)  -> per-jj constant + base,
    //   consecutive k -> consecutive addresses -> conflict-free.
    const int k = tid;  // THREADS == KBINS
    float acc = 0.0f;
    if (k >= 5 && k <= 250) {
        const int b = k - 5;
        #pragma unroll
        for (int jj = 0; jj < TBL; jj++) {
            const int m = jj + 8;
            acc += T[jj] * hist[((m & 15) << 8) + (m >> 4) + b];
        }
    } else {
        const int s0 = 16 * k - 72;
        for (int jj = 0; jj < TBL; jj++) {
            int s = s0 + jj;
            if (s >= 0 && s <= SUBBINS) {
                int a = (s < SUBBINS) ? (((s & 15) << 8) | (s >> 4)) : SUBBINS;
                acc += T[jj] * hist[a];
            }
        }
    }
    atomicAdd(&out[batch * KBINS + k], acc * inv_n);
}

extern "C" void kernel_launch(void* const* d_in, const int* in_sizes, int n_in,
                              void* d_out, int out_size) {
    const float* x = (const float*)d_in[0];
    float* out = (float*)d_out;

    int B  = out_size / KBINS;        // 8
    int N  = in_sizes[0] / B;         // 262144
    int N4 = N / 4;

    zero_kernel<<<(out_size + THREADS - 1) / THREADS, THREADS>>>(out, out_size);

    dim3 grid(P, B);
    hist_kernel<<<grid, THREADS>>>(x, out, N4, 1.0f / (float)N);
}